// round 11
// baseline (speedup 1.0000x reference)
#include <cuda_runtime.h>
#include <cstdint>

#define NROWS  14400   // 16 * 900
#define NC     91
#define MT     1600
#define TN     8
#define NTILES (NROWS / TN)   // 1800
#define CCN    (TN * NC)      // 728
#define GRID   592            // 148 SMs * 4 resident blocks
#define EPSF   1e-8f

__global__ __launch_bounds__(256, 4) void cost_kernel(
    const float* __restrict__ pred_logits, // [NROWS, NC]
    const float* __restrict__ pred_boxes,  // [NROWS, 4] cxcywh
    const int*   __restrict__ tgt_ids,     // [MT] int32
    const float* __restrict__ tgt_bbox,    // [MT, 4] cxcywh
    float*       __restrict__ out)         // [NROWS, MT]
{
    __shared__ float4 s_tb[MT];         // tgt (cx, cy, w/2, h/2) — loaded ONCE
    __shared__ int    s_tid[MT];        // tgt class ids — loaded ONCE
    __shared__ float  s_raw[2][CCN];    // double-buffered raw logits (cp.async dst)
    __shared__ float  s_cc[2][CCN];     // double-buffered focal cost (+1 baked in)
    __shared__ float4 s_pb[2][TN];      // double-buffered pred boxes (raw cxcywh)

    const int tid = threadIdx.x;

    uint32_t raw_base = (uint32_t)__cvta_generic_to_shared(&s_raw[0][0]);
    uint32_t pb_base  = (uint32_t)__cvta_generic_to_shared(&s_pb[0][0]);

    // ---- prefetch helper: raw logits slab + pred boxes for tile t into slot ----
    auto prefetch = [&](int t, int slot) {
        const float* lsrc = pred_logits + (size_t)t * CCN;
        for (int i = tid; i < CCN; i += 256) {
            uint32_t dst = raw_base + (uint32_t)(slot * CCN + i) * 4u;
            asm volatile("cp.async.ca.shared.global [%0], [%1], 4;"
                         :: "r"(dst), "l"(lsrc + i));
        }
        if (tid < TN) {
            uint32_t dst = pb_base + (uint32_t)(slot * TN + tid) * 16u;
            const float* bsrc = pred_boxes + ((size_t)t * TN + tid) * 4;
            asm volatile("cp.async.cg.shared.global [%0], [%1], 16;"
                         :: "r"(dst), "l"(bsrc));
        }
    };

    // ---- prologue: kick off tile-0 prefetch, then load targets once ----
    int t0 = blockIdx.x;
    prefetch(t0, 0);
    asm volatile("cp.async.commit_group;" ::: "memory");

    for (int i = tid; i < MT; i += 256) {
        float4 tb = ((const float4*)tgt_bbox)[i];
        s_tb[i] = make_float4(tb.x, tb.y, 0.5f * tb.z, 0.5f * tb.w);
        int id  = tgt_ids[i];
        s_tid[i] = (id < 0) ? 0 : (id >= NC ? NC - 1 : id);
    }

    int k = 0;
    for (int t = t0; t < NTILES; t += GRID) {
        // prefetch next tile into the other slot (safe: its last readers finished
        // before the previous iteration's post-cc barrier)
        int tn = t + GRID;
        if (tn < NTILES) prefetch(tn, k ^ 1);
        asm volatile("cp.async.commit_group;" ::: "memory");
        asm volatile("cp.async.wait_group 1;" ::: "memory");  // tile t's group done
        __syncthreads();  // raw[k]/pb[k] visible to all; prior compute drained

        // focal-cost prep from prefetched logits (fast-math; +1.0 baked in)
        const float* rawk = s_raw[k];
        float* cck = s_cc[k];
        for (int i = tid; i < CCN; i += 256) {
            float x = rawk[i];
            float e = __expf(-x);
            float p = __fdividef(1.0f, 1.0f + e);
            float omp = 1.0f - p;
            float lp = __logf(p + EPSF);
            float lo = __logf(omp + EPSF);
            cck[i] = fmaf(-0.25f * omp * omp, lp, fmaf(0.75f * p * p, lo, 1.0f));
        }
        __syncthreads();  // cc[k] ready for cross-warp reads

        const int n0 = t * TN;

        // ---- main compute: each thread owns groups of 4 consecutive columns ----
        for (int g = tid; g < MT / 4; g += 256) {
            const int m0 = g * 4;

            float tcx[4], tcy[4], htw[4], hth[4], ta4[4];
            int   idb[4];
#pragma unroll
            for (int j = 0; j < 4; j++) {
                float4 tb = s_tb[m0 + j];
                tcx[j] = tb.x;
                tcy[j] = tb.y;
                htw[j] = tb.z;
                hth[j] = tb.w;
                ta4[j] = 4.0f * tb.z * tb.w;   // full tgt area
                idb[j] = s_tid[m0 + j] * 4;    // byte offset into a cc row
            }

#pragma unroll
            for (int r = 0; r < TN; r++) {
                float4 pbr = s_pb[k][r];
                float pcx = pbr.x, pcy = pbr.y;
                float hpw = 0.5f * pbr.z, hph = 0.5f * pbr.w;
                float pa4 = pbr.z * pbr.w;     // full pred area
                const char* ccrow = (const char*)&cck[r * NC];

                float4 res;
                float* rp = &res.x;
#pragma unroll
                for (int j = 0; j < 4; j++) {
                    float dx = fabsf(pcx - tcx[j]);
                    float dy = fabsf(pcy - tcy[j]);
                    float sx = fabsf(hpw - htw[j]);
                    float sy = fabsf(hph - hth[j]);
                    float cb = fmaf(2.0f, sx + sy, dx + dy);     // L1 cost
                    float ax = hpw + htw[j];
                    float ay = hph + hth[j];
                    float bx = fmaxf(dx, sx);
                    float by = fmaxf(dy, sy);
                    float iw = fmaxf(ax - bx, 0.0f);             // full inter width
                    float ih = fmaxf(ay - by, 0.0f);
                    float inter = iw * ih;
                    float uni   = (pa4 + ta4[j]) - inter;
                    float ea    = (ax + bx) * (ay + by);
                    float denom = uni * ea;
                    float rd;
                    asm("rcp.approx.f32 %0, %1;" : "=f"(rd) : "f"(denom));
                    float iou = inter * ea * rd;
                    float q   = uni * uni * rd;
                    float cc1 = *(const float*)(ccrow + idb[j]); // cc + 1
                    rp[j] = (cb + cc1) - (iou + q);
                }
                ((float4*)out)[((size_t)(n0 + r) * MT + m0) >> 2] = res;
            }
        }
        k ^= 1;
    }
}

extern "C" void kernel_launch(void* const* d_in, const int* in_sizes, int n_in,
                              void* d_out, int out_size) {
    const float* pred_logits = (const float*)d_in[0];  // [16,900,91]
    const float* pred_boxes  = (const float*)d_in[1];  // [16,900,4]
    const int*   tgt_ids     = (const int*)d_in[2];    // [1600] int32
    const float* tgt_bbox    = (const float*)d_in[3];  // [1600,4]
    float*       out         = (float*)d_out;          // [16,900,1600]

    cost_kernel<<<GRID, 256>>>(pred_logits, pred_boxes, tgt_ids, tgt_bbox, out);
}

// round 12
// speedup vs baseline: 1.1788x; 1.1788x over previous
#include <cuda_runtime.h>

#define NROWS 14400   // 16 * 900
#define NC    91
#define MT    1600
#define TN    12      // rows per block: grid=1200 -> 2.03 waves at 4 blocks/SM
#define EPSF  1e-8f

__global__ __launch_bounds__(256, 4) void cost_kernel(
    const float* __restrict__ pred_logits, // [NROWS, NC]
    const float* __restrict__ pred_boxes,  // [NROWS, 4] cxcywh
    const int*   __restrict__ tgt_ids,     // [MT] int32
    const float* __restrict__ tgt_bbox,    // [MT, 4] cxcywh
    float*       __restrict__ out)         // [NROWS, MT]
{
    __shared__ float4 s_tb[MT];        // tgt (cx, cy, w/2, h/2)
    __shared__ int    s_tid[MT];       // tgt class ids
    __shared__ float  s_cc[TN * NC];   // focal cost slice, +1.0 baked in
    __shared__ float4 s_pb[TN];        // pred (cx, cy, w/2, h/2)

    const int tid = threadIdx.x;
    const int n0  = blockIdx.x * TN;

    for (int i = tid; i < MT; i += 256) {
        float4 tb = ((const float4*)tgt_bbox)[i];
        s_tb[i] = make_float4(tb.x, tb.y, 0.5f * tb.z, 0.5f * tb.w);
        int id  = tgt_ids[i];
        s_tid[i] = (id < 0) ? 0 : (id >= NC ? NC - 1 : id);
    }
    // Fused focal-cost prep (fast-math). Stores cc + 1.0.
    for (int i = tid; i < TN * NC; i += 256) {
        float x = pred_logits[n0 * NC + i];
        float e = __expf(-x);
        float p = __fdividef(1.0f, 1.0f + e);
        float omp = 1.0f - p;
        float lp = __logf(p + EPSF);
        float lo = __logf(omp + EPSF);
        s_cc[i] = fmaf(-0.25f * omp * omp, lp, fmaf(0.75f * p * p, lo, 1.0f));
    }
    if (tid < TN) {
        float4 pb = ((const float4*)pred_boxes)[n0 + tid];
        s_pb[tid] = make_float4(pb.x, pb.y, 0.5f * pb.z, 0.5f * pb.w);
    }
    __syncthreads();

    // Each thread owns groups of 4 consecutive target columns (float4 stores).
    for (int g = tid; g < MT / 4; g += 256) {
        const int m0 = g * 4;

        // Per-column cache: cx, cy, hw, hh, full tgt area, class byte offset
        float tcx[4], tcy[4], htw[4], hth[4], ta4[4];
        int   idb[4];
#pragma unroll
        for (int j = 0; j < 4; j++) {
            float4 tb = s_tb[m0 + j];
            tcx[j] = tb.x;
            tcy[j] = tb.y;
            htw[j] = tb.z;
            hth[j] = tb.w;
            ta4[j] = 4.0f * tb.z * tb.w;   // full tgt area
            idb[j] = s_tid[m0 + j] * 4;    // byte offset into a cc row
        }

#pragma unroll
        for (int r = 0; r < TN; r++) {
            float4 pbr = s_pb[r];
            float pcx = pbr.x, pcy = pbr.y;
            float hpw = pbr.z, hph = pbr.w;
            float pa4 = 4.0f * hpw * hph;  // full pred area
            const char* ccrow = (const char*)&s_cc[r * NC];

            float4 res;
            float* rp = &res.x;
#pragma unroll
            for (int j = 0; j < 4; j++) {
                // Shared |diff| terms (serve both L1 cost and geometry)
                float dx = fabsf(pcx - tcx[j]);
                float dy = fabsf(pcy - tcy[j]);
                float sx = fabsf(hpw - htw[j]);   // 0.5|pw - tw|
                float sy = fabsf(hph - hth[j]);
                // L1: dx + dy + 2(sx + sy)
                float cb = fmaf(2.0f, sx + sy, dx + dy);
                // Interval identity (halves cancel): overlap_w = (hpw+htw) - max(dx, sx)
                float ax = hpw + htw[j];
                float ay = hph + hth[j];
                float bx = fmaxf(dx, sx);
                float by = fmaxf(dy, sy);
                float iw = fmaxf(ax - bx, 0.0f);  // full intersection width
                float ih = fmaxf(ay - by, 0.0f);
                float inter = iw * ih;                    // full intersection area
                float uni   = (pa4 + ta4[j]) - inter;     // full union
                float ea    = (ax + bx) * (ay + by);      // full enclosing area
                // One reciprocal serves both ratios:
                //   iou = inter*ea * rcp(uni*ea),  q = uni/ea = uni*uni * rcp(uni*ea)
                float denom = uni * ea;
                float rd;
                asm("rcp.approx.f32 %0, %1;" : "=f"(rd) : "f"(denom));
                float iou = inter * ea * rd;
                float q   = uni * uni * rd;
                // cost = cb + (cc+1) - iou - q   (the +1 is baked into s_cc)
                float cc1 = *(const float*)(ccrow + idb[j]);   // LDS [reg + imm]
                rp[j] = (cb + cc1) - (iou + q);
            }
            ((float4*)out)[((size_t)(n0 + r) * MT + m0) >> 2] = res;
        }
    }
}

extern "C" void kernel_launch(void* const* d_in, const int* in_sizes, int n_in,
                              void* d_out, int out_size) {
    const float* pred_logits = (const float*)d_in[0];  // [16,900,91]
    const float* pred_boxes  = (const float*)d_in[1];  // [16,900,4]
    const int*   tgt_ids     = (const int*)d_in[2];    // [1600] int32
    const float* tgt_bbox    = (const float*)d_in[3];  // [1600,4]
    float*       out         = (float*)d_out;          // [16,900,1600]

    cost_kernel<<<NROWS / TN, 256>>>(pred_logits, pred_boxes, tgt_ids, tgt_bbox, out);
}